// round 1
// baseline (speedup 1.0000x reference)
#include <cuda_runtime.h>

#define NB 8
#define NQ 128
#define NK 512
#define ND 512     // d_q == d_kv
#define DA 256     // d_attn

// ---------------- scratch (static device allocations; no cudaMalloc) ----------
__device__ float g_Wt[1024 * DA];          // W transposed: [d (1024)][a (256)]
__device__ float g_qp[NB * NQ * DA];       // q_proj + bias
__device__ float g_kp[NB * NK * DA];       // k_proj
__device__ float g_kvpart[NB * 8 * ND];    // partial kv sums (8 segments of 64 k)

// ---------------- W transpose: W(256 x 1024) -> Wt(1024 x 256) ----------------
__global__ void transpose_w(const float* __restrict__ W) {
    __shared__ float tile[32][33];
    const int d0 = blockIdx.x * 32;
    const int a0 = blockIdx.y * 32;
    const int tx = threadIdx.x, ty = threadIdx.y;  // (32, 8)
#pragma unroll
    for (int j = 0; j < 32; j += 8)
        tile[ty + j][tx] = W[(a0 + ty + j) * 1024 + d0 + tx];
    __syncthreads();
#pragma unroll
    for (int j = 0; j < 32; j += 8)
        g_Wt[(d0 + ty + j) * DA + a0 + tx] = tile[tx][ty + j];
}

// ---------------- projection GEMM: Out[m,a] = sum_d X[m,d] * Wt[doff+d][a] ----
// BM=64, BN=64, BK=16, 256 threads, 4x4 per thread. Early-exits tiles whose
// rows are fully masked (never read downstream).
__global__ __launch_bounds__(256) void proj_gemm(
    const float* __restrict__ X, const float* __restrict__ bias,
    float* __restrict__ Out, int doff, int rows_per_b,
    const int* __restrict__ lens)
{
    const int a0 = blockIdx.x * 64;
    const int m0 = blockIdx.y * 64;
    const int b  = m0 / rows_per_b;
    const int r0 = m0 % rows_per_b;
    if (r0 >= lens[b]) return;   // whole tile masked

    __shared__ float As[16][68];
    __shared__ float Bs[16][68];
    const int tid = threadIdx.x;
    const int tx = tid & 15, ty = tid >> 4;

    // A-load mapping: 64 rows x 16 cols, one float4 per thread
    const int ar = tid >> 2;
    const int ac = (tid & 3) * 4;
    // B-load mapping: 16 rows x 64 cols, one float4 per thread
    const int bd = tid >> 4;
    const int bf = (tid & 15) * 4;

    float acc[4][4] = {};

    for (int d0 = 0; d0 < ND; d0 += 16) {
        float4 av = *(const float4*)(X + (m0 + ar) * ND + d0 + ac);
        float4 bv = *(const float4*)(g_Wt + (doff + d0 + bd) * DA + a0 + bf);
        As[ac + 0][ar] = av.x; As[ac + 1][ar] = av.y;
        As[ac + 2][ar] = av.z; As[ac + 3][ar] = av.w;
        *(float4*)&Bs[bd][bf] = bv;
        __syncthreads();
#pragma unroll
        for (int kk = 0; kk < 16; kk++) {
            float4 afv = *(const float4*)&As[kk][ty * 4];
            float4 bfv = *(const float4*)&Bs[kk][tx * 4];
            float aa[4] = {afv.x, afv.y, afv.z, afv.w};
            float bb[4] = {bfv.x, bfv.y, bfv.z, bfv.w};
#pragma unroll
            for (int i = 0; i < 4; i++)
#pragma unroll
                for (int j = 0; j < 4; j++)
                    acc[i][j] += aa[i] * bb[j];
        }
        __syncthreads();
    }

    float badd[4] = {0.f, 0.f, 0.f, 0.f};
    if (bias) {
        badd[0] = bias[a0 + tx * 4 + 0];
        badd[1] = bias[a0 + tx * 4 + 1];
        badd[2] = bias[a0 + tx * 4 + 2];
        badd[3] = bias[a0 + tx * 4 + 3];
    }
#pragma unroll
    for (int i = 0; i < 4; i++) {
        const int m = m0 + ty * 4 + i;
        float4 o;
        o.x = acc[i][0] + badd[0];
        o.y = acc[i][1] + badd[1];
        o.z = acc[i][2] + badd[2];
        o.w = acc[i][3] + badd[3];
        *(float4*)(Out + m * DA + a0 + tx * 4) = o;
    }
}

// ---------------- kv partial sums for masked-q rows -----------------------------
__global__ void kv_partial(const float* __restrict__ kv) {
    const int b = blockIdx.x, seg = blockIdx.y;   // (8, 8)
    const int d = threadIdx.x;                    // 512
    const float* p = kv + (size_t)(b * NK + seg * 64) * ND + d;
    float s = 0.f;
#pragma unroll 8
    for (int k = 0; k < 64; k++) s += p[k * ND];
    g_kvpart[(b * 8 + seg) * ND + d] = s;
}

// ---------------- accurate, cheap tanh: 2 MUFU + 3 fma-pipe ops -----------------
// tanh(x) = 1 - 2/(1+e^{2x}); inf-safe at both ends, ~1e-6 accurate.
__device__ __forceinline__ float fast_tanh(float x) {
    float t = __expf(2.0f * x);
    return 1.0f - __fdividef(2.0f, 1.0f + t);
}

// ---------------- main fused kernel: score + softmax + attn@kv ------------------
__global__ __launch_bounds__(256) void attn_main(
    const float* __restrict__ kv, const float* __restrict__ vvec,
    const int* __restrict__ qlen_p, const int* __restrict__ klen_p,
    float* __restrict__ out)
{
    const int q = blockIdx.x, b = blockIdx.y;
    const int tid = threadIdx.x;
    const int qlen = qlen_p[b];
    const int klen = klen_p[b];
    float* outrow = out + (size_t)(b * NQ + q) * ND;

    if (q >= qlen) {
        // fully-masked query row: softmax over constant -> uniform over ALL k
        for (int d = tid; d < ND; d += 256) {
            float s = 0.f;
#pragma unroll
            for (int g = 0; g < 8; g++) s += g_kvpart[(b * 8 + g) * ND + d];
            outrow[d] = s * (1.0f / (float)NK);
        }
        return;
    }

    __shared__ float sc[NK];
    __shared__ float red[8];
    const int w = tid >> 5, lane = tid & 31;

    // lane l owns attention dims a = 8l .. 8l+7 (registers)
    const float* qprow = g_qp + (size_t)(b * NQ + q) * DA + lane * 8;
    const float4 q0 = *(const float4*)qprow;
    const float4 q1 = *(const float4*)(qprow + 4);
    const float4 v0 = *(const float4*)(vvec + lane * 8);
    const float4 v1 = *(const float4*)(vvec + lane * 8 + 4);

    // ---- scores: warp w handles k = w, w+8, ...
    for (int k = w; k < klen; k += 8) {
        const float* kprow = g_kp + (size_t)(b * NK + k) * DA + lane * 8;
        const float4 c0 = *(const float4*)kprow;
        const float4 c1 = *(const float4*)(kprow + 4);
        float s;
        s  = v0.x * fast_tanh(q0.x + c0.x);
        s += v0.y * fast_tanh(q0.y + c0.y);
        s += v0.z * fast_tanh(q0.z + c0.z);
        s += v0.w * fast_tanh(q0.w + c0.w);
        s += v1.x * fast_tanh(q1.x + c1.x);
        s += v1.y * fast_tanh(q1.y + c1.y);
        s += v1.z * fast_tanh(q1.z + c1.z);
        s += v1.w * fast_tanh(q1.w + c1.w);
#pragma unroll
        for (int o = 16; o; o >>= 1) s += __shfl_xor_sync(0xffffffffu, s, o);
        if (lane == 0) sc[k] = s;
    }
    __syncthreads();

    // ---- softmax over sc[0..klen)
    float lmax = -1e30f;
    for (int k = tid; k < klen; k += 256) lmax = fmaxf(lmax, sc[k]);
#pragma unroll
    for (int o = 16; o; o >>= 1) lmax = fmaxf(lmax, __shfl_xor_sync(0xffffffffu, lmax, o));
    if (lane == 0) red[w] = lmax;
    __syncthreads();
    float m = red[0];
#pragma unroll
    for (int i = 1; i < 8; i++) m = fmaxf(m, red[i]);
    __syncthreads();

    float lsum = 0.f;
    for (int k = tid; k < klen; k += 256) {
        float e = __expf(sc[k] - m);
        sc[k] = e;
        lsum += e;
    }
#pragma unroll
    for (int o = 16; o; o >>= 1) lsum += __shfl_xor_sync(0xffffffffu, lsum, o);
    if (lane == 0) red[w] = lsum;
    __syncthreads();
    float Z = 0.f;
#pragma unroll
    for (int i = 0; i < 8; i++) Z += red[i];
    const float inv = __fdividef(1.0f, Z);

    // ---- out = (attn @ kv) ; thread owns d = tid and tid+256
    const float* kvb = kv + (size_t)b * NK * ND;
    float acc0 = 0.f, acc1 = 0.f;
    int k = 0;
    for (; k + 4 <= klen; k += 4) {
#pragma unroll
        for (int u = 0; u < 4; u++) {
            const float p = sc[k + u];
            acc0 += p * kvb[(k + u) * ND + tid];
            acc1 += p * kvb[(k + u) * ND + 256 + tid];
        }
    }
    for (; k < klen; k++) {
        const float p = sc[k];
        acc0 += p * kvb[k * ND + tid];
        acc1 += p * kvb[k * ND + 256 + tid];
    }
    outrow[tid]       = acc0 * inv;
    outrow[tid + 256] = acc1 * inv;
}

// ---------------- launch --------------------------------------------------------
extern "C" void kernel_launch(void* const* d_in, const int* in_sizes, int n_in,
                              void* d_out, int out_size)
{
    const float* query = (const float*)d_in[0];
    const float* kv    = (const float*)d_in[1];
    const float* W     = (const float*)d_in[2];
    const float* bias  = (const float*)d_in[3];
    const float* v     = (const float*)d_in[4];
    const int*   qlen  = (const int*)d_in[5];
    const int*   klen  = (const int*)d_in[6];
    float* out = (float*)d_out;

    float *Wt, *qp, *kp;
    cudaGetSymbolAddress((void**)&Wt, g_Wt);
    cudaGetSymbolAddress((void**)&qp, g_qp);
    cudaGetSymbolAddress((void**)&kp, g_kp);
    (void)Wt;

    transpose_w<<<dim3(32, 8), dim3(32, 8)>>>(W);
    // q_proj (+bias): M = 8*128 = 1024 rows
    proj_gemm<<<dim3(DA / 64, (NB * NQ) / 64), 256>>>(query, bias, qp, 0,   NQ, qlen);
    // k_proj: M = 8*512 = 4096 rows
    proj_gemm<<<dim3(DA / 64, (NB * NK) / 64), 256>>>(kv,    nullptr, kp, 512, NK, klen);
    kv_partial<<<dim3(NB, 8), ND>>>(kv);
    attn_main<<<dim3(NQ, NB), 256>>>(kv, v, qlen, klen, out);
}